// round 2
// baseline (speedup 1.0000x reference)
#include <cuda_runtime.h>
#include <math.h>

// ---------------------------------------------------------------------------
// Problem constants
// ---------------------------------------------------------------------------
#define BB   8      // batch
#define CC   256    // dim
#define HH   40     // pooled height
#define WW   40     // pooled width
#define LL   1600   // tokens per batch (40*40)
#define NH   8      // heads
#define HD   32     // head dim
#define HID  1024   // mlp hidden
#define HIRES 160   // low spatial
#define HRES  80    // high spatial

// ---------------------------------------------------------------------------
// Scratch (static __device__ globals; no runtime allocation)
// ---------------------------------------------------------------------------
__device__ float g_posT [CC * LL];
__device__ float g_resid[BB * CC * LL];
__device__ float g_lowpe[BB * CC * LL];
__device__ float g_highpe[BB * CC * LL];
__device__ float g_Q[BB * CC * LL];
__device__ float g_K[BB * CC * LL];
__device__ float g_V[BB * CC * LL];
__device__ float g_qscale[BB * CC];
__device__ float g_kscale[BB * CC];
__device__ float g_KV[BB * NH * HD * HD];
__device__ float g_attn[BB * CC * LL];
__device__ float g_o[BB * CC * LL];
__device__ float g_res2[BB * CC * LL];
__device__ float g_h[BB * HID * LL];
__device__ float g_m[BB * CC * LL];
__device__ float g_final[BB * CC * LL];

// ---------------------------------------------------------------------------
// 1) Positional embedding, transposed: posT[c][l]
// ---------------------------------------------------------------------------
__global__ void pos_kernel() {
    int idx = blockIdx.x * 256 + threadIdx.x;
    if (idx >= CC * LL) return;
    int c = idx / LL;
    int l = idx % LL;
    int g = c >> 6;
    int j = c & 63;
    float om  = __powf(10000.0f, -(float)j / 64.0f);
    float coord = (g < 2) ? (float)(l / WW) : (float)(l % WW);
    float arg = coord * om;
    g_posT[idx] = (g & 1) ? cosf(arg) : sinf(arg);
}

// ---------------------------------------------------------------------------
// 2) Pooling
// ---------------------------------------------------------------------------
__global__ void pool_low_kernel(const float* __restrict__ low) {
    int bc = blockIdx.x;
    int c  = bc % CC;
    const float* src = low + (size_t)bc * HIRES * HIRES;
    for (int l = threadIdx.x; l < LL; l += 256) {
        int ih = l / WW, iw = l % WW;
        float s = 0.f;
        #pragma unroll
        for (int r = 0; r < 4; r++) {
            const float* row = src + (4 * ih + r) * HIRES + 4 * iw;
            s += row[0] + row[1] + row[2] + row[3];
        }
        float m = s * 0.0625f;
        size_t o = (size_t)bc * LL + l;
        g_resid[o] = m;
        g_lowpe[o] = m + g_posT[c * LL + l];
    }
}

__global__ void pool_high_kernel(const float* __restrict__ high) {
    int bc = blockIdx.x;
    int c  = bc % CC;
    const float* src = high + (size_t)bc * HRES * HRES;
    for (int l = threadIdx.x; l < LL; l += 256) {
        int ih = l / WW, iw = l % WW;
        const float* r0 = src + (2 * ih) * HRES + 2 * iw;
        const float* r1 = r0 + HRES;
        float m = (r0[0] + r0[1] + r1[0] + r1[1]) * 0.25f;
        g_highpe[(size_t)bc * LL + l] = m + g_posT[c * LL + l];
    }
}

// ---------------------------------------------------------------------------
// 3) Channel-major SGEMM: Y[b][m][l] = sum_k A[m][k] * X[b][k][l] + bias[m]
//    64x64 tile, k-step 16, 256 threads, 4x4 micro-tile, float4 smem reads.
// ---------------------------------------------------------------------------
template<int EPI, int SRC, int DST>
__global__ void sgemm_cm(const float* __restrict__ A,
                         const float* __restrict__ bias,
                         int M, int K) {
    const float* X = (SRC == 0) ? g_lowpe :
                     (SRC == 1) ? g_highpe :
                     (SRC == 2) ? g_attn :
                     (SRC == 3) ? g_res2 : g_h;
    float* Y = (DST == 0) ? g_Q :
               (DST == 1) ? g_K :
               (DST == 2) ? g_V :
               (DST == 3) ? g_o :
               (DST == 4) ? g_h : g_m;

    __shared__ float As[16][68];   // [k][m], stride 68 -> float4-aligned rows
    __shared__ float Bs[16][64];   // [k][n]

    int b  = blockIdx.z;
    int m0 = blockIdx.y * 64;
    int n0 = blockIdx.x * 64;
    const float* Xb = X + (size_t)b * K * LL;
    float*       Yb = Y + (size_t)b * M * LL;

    int tid = threadIdx.x;
    int tx = tid % 16, ty = tid / 16;
    int ar = tid / 16, ac = tid % 16;        // A: 16 m-rows/pass x 16 k
    int b_r = tid / 16, b_c4 = (tid % 16) * 4; // B: one float4 per thread per pass

    float acc[4][4];
    #pragma unroll
    for (int i = 0; i < 4; i++)
        #pragma unroll
        for (int j = 0; j < 4; j++) acc[i][j] = 0.f;

    for (int k0 = 0; k0 < K; k0 += 16) {
        #pragma unroll
        for (int i = 0; i < 4; i++)
            As[ac][ar + i * 16] = A[(size_t)(m0 + ar + i * 16) * K + k0 + ac];
        // B tile: 16 rows x 64 cols = 256 float4, one per thread
        float4 bv4 = *(const float4*)(Xb + (size_t)(k0 + b_r) * LL + n0 + b_c4);
        *(float4*)&Bs[b_r][b_c4] = bv4;
        __syncthreads();
        #pragma unroll
        for (int k = 0; k < 16; k++) {
            float4 a4 = *(const float4*)&As[k][ty * 4];
            float4 b4 = *(const float4*)&Bs[k][tx * 4];
            float a[4] = {a4.x, a4.y, a4.z, a4.w};
            float bb[4] = {b4.x, b4.y, b4.z, b4.w};
            #pragma unroll
            for (int i = 0; i < 4; i++)
                #pragma unroll
                for (int j = 0; j < 4; j++)
                    acc[i][j] = fmaf(a[i], bb[j], acc[i][j]);
        }
        __syncthreads();
    }

    #pragma unroll
    for (int i = 0; i < 4; i++) {
        int m = m0 + ty * 4 + i;
        float bsc = bias[m];
        float4 o4;
        float* ov = &o4.x;
        #pragma unroll
        for (int j = 0; j < 4; j++) {
            float v = acc[i][j] + bsc;
            if (EPI == 1)
                v = 0.5f * v * (1.0f + erff(v * 0.70710678118654752f));
            ov[j] = v;
        }
        *(float4*)(Yb + (size_t)m * LL + n0 + tx * 4) = o4;
    }
}

// ---------------------------------------------------------------------------
// 4) L1-norm scales over sequence
// ---------------------------------------------------------------------------
__global__ void abssum_kernel() {
    int bc = blockIdx.x;
    const float* src = ((blockIdx.y == 0) ? g_Q : g_K) + (size_t)bc * LL;
    float s = 0.f;
    for (int l = threadIdx.x; l < LL; l += 256) s += fabsf(src[l]);
    __shared__ float red[256];
    red[threadIdx.x] = s;
    __syncthreads();
    for (int o = 128; o > 0; o >>= 1) {
        if (threadIdx.x < o) red[threadIdx.x] += red[threadIdx.x + o];
        __syncthreads();
    }
    if (threadIdx.x == 0) {
        float sc = 1.0f / fmaxf(red[0], 1e-6f);
        ((blockIdx.y == 0) ? g_qscale : g_kscale)[bc] = sc;
    }
}

// ---------------------------------------------------------------------------
// 5) KV[n][d][m] with folded Q/K L1 normalizers
// ---------------------------------------------------------------------------
__global__ void kv_kernel() {
    int n = blockIdx.x;
    int b = n / NH, h = n % NH;
    int chbase = h * HD;
    const float* Kp = g_K + ((size_t)b * CC + chbase) * LL;
    const float* Vp = g_V + ((size_t)b * CC + chbase) * LL;

    __shared__ float Ks[32][33], Vs[32][33];
    int row = threadIdx.x / 32, col = threadIdx.x % 32;
    float acc = 0.f;
    for (int l0 = 0; l0 < LL; l0 += 32) {
        Ks[row][col] = Kp[(size_t)row * LL + l0 + col];
        Vs[row][col] = Vp[(size_t)row * LL + l0 + col];
        __syncthreads();
        #pragma unroll
        for (int lc = 0; lc < 32; lc++)
            acc = fmaf(Ks[row][lc], Vs[col][lc], acc);
        __syncthreads();
    }
    float sc = g_kscale[b * CC + chbase + row] * g_qscale[b * CC + chbase + row];
    g_KV[((size_t)n * HD + row) * HD + col] = acc * sc;
}

// ---------------------------------------------------------------------------
// 6) attn = Q @ KV, fused RMSNorm over head dim
// ---------------------------------------------------------------------------
__global__ void attn_kernel(const float* __restrict__ rms_w) {
    int n  = blockIdx.y;
    int l0 = blockIdx.x * 32;
    int b = n / NH, h = n % NH;
    int chbase = h * HD;

    __shared__ float KVs[32][33], Qs[32][33], S[32][33];
    int row = threadIdx.x / 32, col = threadIdx.x % 32;

    KVs[row][col] = g_KV[((size_t)n * HD + row) * HD + col];
    const float* Qp = g_Q + ((size_t)b * CC + chbase) * LL;
    Qs[row][col] = Qp[(size_t)row * LL + l0 + col];
    __syncthreads();

    float acc = 0.f;
    #pragma unroll
    for (int d = 0; d < 32; d++)
        acc = fmaf(Qs[d][col], KVs[d][row], acc);
    S[row][col] = acc;
    __syncthreads();

    float ss = 0.f;
    #pragma unroll
    for (int mm = 0; mm < 32; mm++) { float v = S[mm][col]; ss = fmaf(v, v, ss); }
    float r = rsqrtf(ss * (1.0f / 32.0f) + 1.1920929e-07f);

    g_attn[((size_t)b * CC + chbase + row) * LL + l0 + col] = acc * r * rms_w[row];
}

// ---------------------------------------------------------------------------
// 7) Token LayerNorm + residual (column LN in channel-major layout)
// ---------------------------------------------------------------------------
template<int SRC>
__global__ void ln_res_kernel(const float* __restrict__ w, const float* __restrict__ bias) {
    const float* X = (SRC == 0) ? g_o     : g_m;
    const float* R = (SRC == 0) ? g_resid : g_res2;
    float*       Y = (SRC == 0) ? g_res2  : g_final;

    int b = blockIdx.y;
    int l = blockIdx.x * 256 + threadIdx.x;
    if (l >= LL) return;

    const float* Xb = X + (size_t)b * CC * LL + l;
    float s = 0.f, ss = 0.f;
    for (int c = 0; c < CC; c++) {
        float v = Xb[(size_t)c * LL];
        s += v; ss = fmaf(v, v, ss);
    }
    float mean = s * (1.0f / CC);
    float var  = ss * (1.0f / CC) - mean * mean;
    float rstd = rsqrtf(var + 1e-5f);

    const float* Rb = R + (size_t)b * CC * LL + l;
    float*       Yb = Y + (size_t)b * CC * LL + l;
    for (int c = 0; c < CC; c++) {
        float v = Xb[(size_t)c * LL];
        Yb[(size_t)c * LL] = Rb[(size_t)c * LL] + (v - mean) * rstd * w[c] + bias[c];
    }
}

// ---------------------------------------------------------------------------
// 8) Bilinear 4x upsample (half-pixel, clamped) * original low
// ---------------------------------------------------------------------------
__global__ void resize_mul_kernel(const float* __restrict__ low, float* __restrict__ out) {
    int bc = blockIdx.x;
    __shared__ float P[LL];
    const float* Fp = g_final + (size_t)bc * LL;
    for (int i = threadIdx.x; i < LL; i += 256) P[i] = Fp[i];
    __syncthreads();

    const float* lp = low + (size_t)bc * HIRES * HIRES;
    float*       op = out + (size_t)bc * HIRES * HIRES;
    for (int idx = threadIdx.x; idx < HIRES * HIRES; idx += 256) {
        int y = idx / HIRES, x = idx % HIRES;
        float sy = y * 0.25f - 0.375f;
        float sx = x * 0.25f - 0.375f;
        int y0 = (int)floorf(sy); float fy = sy - y0;
        int x0 = (int)floorf(sx); float fx = sx - x0;
        int y1 = min(y0 + 1, HH - 1); y0 = max(y0, 0);
        int x1 = min(x0 + 1, WW - 1); x0 = max(x0, 0);
        float v00 = P[y0 * WW + x0], v01 = P[y0 * WW + x1];
        float v10 = P[y1 * WW + x0], v11 = P[y1 * WW + x1];
        float v = v00 * (1.f - fy) * (1.f - fx) + v01 * (1.f - fy) * fx
                + v10 * fy * (1.f - fx)         + v11 * fy * fx;
        op[idx] = v * lp[idx];
    }
}

// ---------------------------------------------------------------------------
// Launch
// ---------------------------------------------------------------------------
extern "C" void kernel_launch(void* const* d_in, const int* in_sizes, int n_in,
                              void* d_out, int out_size) {
    const float* low  = (const float*)d_in[0];
    const float* high = (const float*)d_in[1];
    const float* q_w = (const float*)d_in[2];  const float* q_b = (const float*)d_in[3];
    const float* k_w = (const float*)d_in[4];  const float* k_b = (const float*)d_in[5];
    const float* v_w = (const float*)d_in[6];  const float* v_b = (const float*)d_in[7];
    const float* o_w = (const float*)d_in[8];  const float* o_b = (const float*)d_in[9];
    const float* rms_w = (const float*)d_in[10];
    const float* l1_w = (const float*)d_in[11]; const float* l1_b = (const float*)d_in[12];
    const float* l2_w = (const float*)d_in[13]; const float* l2_b = (const float*)d_in[14];
    const float* n1_w = (const float*)d_in[15]; const float* n1_b = (const float*)d_in[16];
    const float* n2_w = (const float*)d_in[17]; const float* n2_b = (const float*)d_in[18];
    float* out = (float*)d_out;

    pos_kernel<<<(CC * LL) / 256, 256>>>();
    pool_low_kernel <<<BB * CC, 256>>>(low);
    pool_high_kernel<<<BB * CC, 256>>>(high);

    dim3 gP(LL / 64, CC / 64, BB);
    sgemm_cm<0, 0, 0><<<gP, 256>>>(q_w, q_b, CC, CC);
    sgemm_cm<0, 1, 1><<<gP, 256>>>(k_w, k_b, CC, CC);
    sgemm_cm<0, 1, 2><<<gP, 256>>>(v_w, v_b, CC, CC);

    abssum_kernel<<<dim3(BB * CC, 2), 256>>>();
    kv_kernel<<<BB * NH, 1024>>>();
    attn_kernel<<<dim3(LL / 32, BB * NH), 1024>>>(rms_w);

    sgemm_cm<0, 2, 3><<<gP, 256>>>(o_w, o_b, CC, CC);
    ln_res_kernel<0><<<dim3((LL + 255) / 256, BB), 256>>>(n1_w, n1_b);

    dim3 gH(LL / 64, HID / 64, BB);
    sgemm_cm<1, 3, 4><<<gH, 256>>>(l1_w, l1_b, HID, CC);
    sgemm_cm<0, 4, 5><<<gP, 256>>>(l2_w, l2_b, CC, HID);
    ln_res_kernel<1><<<dim3((LL + 255) / 256, BB), 256>>>(n2_w, n2_b);

    resize_mul_kernel<<<BB * CC, 256>>>(low, out);
}